// round 13
// baseline (speedup 1.0000x reference)
#include <cuda_runtime.h>

// hidden [4096] f32, encoder_outputs [8192,1,4096] f32
// energies = enc @ hidden -> softmax -> output = enc^T @ attn
// d_out: [0:4096) = output, [4096:12288) = attn
//
// SINGLE persistent kernel: 256 blocks (all co-resident at 2 CTAs/SM),
// grouped online-softmax accumulation, software grid barrier (phase flip),
// then atomic-free combine: each block owns 16 output columns + 32 attn rows.

#define SEQ_LEN 8192
#define HIDDEN  4096
#define H4      (HIDDEN / 4)
#define NBLK    256
#define ROWS    (SEQ_LEN / NBLK)   // 32 rows per block
#define GRP     4                  // rows per inner group
#define NGRP    (ROWS / GRP)       // 8

__device__ float g_energies[SEQ_LEN];
__device__ float g_partial[(size_t)NBLK * HIDDEN];
__device__ float g_m[NBLK];
__device__ float g_l[NBLK];
__device__ int   g_count;          // arrivals; reset by last block
__device__ int   g_phase;          // monotonically increasing release flag

// ---------------------------------------------------------------------------
__global__ __launch_bounds__(256, 2) void attn_fused(
    const float* __restrict__ enc, const float* __restrict__ hidden,
    float* __restrict__ out, float* __restrict__ attn)
{
    const int tid  = threadIdx.x;
    const int wid  = tid >> 5;
    const int lane = tid & 31;
    const int bid  = blockIdx.x;
    const int r0   = bid * ROWS;

    __shared__ float  sred[2][GRP][8];
    __shared__ float4 sacc[256][4];      // 16 KB combine tree
    __shared__ float  red2[8];
    __shared__ float  sM, sZ;
    __shared__ int    s_phase;

    // snapshot release phase BEFORE doing any work
    if (tid == 0) s_phase = *(volatile int*)&g_phase;
    __syncthreads();
    const int myphase = s_phase;

    // ---- phase A: grouped online-softmax accumulation over 32 rows --------
    const float4* h4 = reinterpret_cast<const float4*>(hidden);
    float4 hv0 = h4[tid];
    float4 hv1 = h4[tid + 256];
    float4 hv2 = h4[tid + 512];
    float4 hv3 = h4[tid + 768];

    float4 acc[4];
    #pragma unroll
    for (int k = 0; k < 4; ++k) acc[k] = make_float4(0.f, 0.f, 0.f, 0.f);
    float m = -3.4e38f;
    float l = 0.f;

    #pragma unroll 1
    for (int g = 0; g < NGRP; ++g) {
        const int rg = r0 + g * GRP;

        float4 d[GRP][4];
        #pragma unroll
        for (int s = 0; s < GRP; ++s) {
            const float4* b = reinterpret_cast<const float4*>(enc + (size_t)(rg + s) * HIDDEN);
            d[s][0] = b[tid];
            d[s][1] = b[tid + 256];
            d[s][2] = b[tid + 512];
            d[s][3] = b[tid + 768];
        }

        float dot[GRP];
        #pragma unroll
        for (int s = 0; s < GRP; ++s) {
            dot[s] = d[s][0].x*hv0.x + d[s][0].y*hv0.y + d[s][0].z*hv0.z + d[s][0].w*hv0.w
                   + d[s][1].x*hv1.x + d[s][1].y*hv1.y + d[s][1].z*hv1.z + d[s][1].w*hv1.w
                   + d[s][2].x*hv2.x + d[s][2].y*hv2.y + d[s][2].z*hv2.z + d[s][2].w*hv2.w
                   + d[s][3].x*hv3.x + d[s][3].y*hv3.y + d[s][3].z*hv3.z + d[s][3].w*hv3.w;
        }
        #pragma unroll
        for (int off = 16; off > 0; off >>= 1) {
            #pragma unroll
            for (int s = 0; s < GRP; ++s)
                dot[s] += __shfl_down_sync(0xFFFFFFFFu, dot[s], off);
        }
        if (lane == 0) {
            #pragma unroll
            for (int s = 0; s < GRP; ++s) sred[g & 1][s][wid] = dot[s];
        }
        __syncthreads();

        float e[GRP];
        #pragma unroll
        for (int s = 0; s < GRP; ++s)
            e[s] = sred[g & 1][s][0] + sred[g & 1][s][1] + sred[g & 1][s][2] + sred[g & 1][s][3]
                 + sred[g & 1][s][4] + sred[g & 1][s][5] + sred[g & 1][s][6] + sred[g & 1][s][7];
        if (tid < GRP) g_energies[rg + tid] = e[tid];

        float mg = fmaxf(fmaxf(e[0], e[1]), fmaxf(e[2], e[3]));
        float mn = fmaxf(m, mg);
        float sc = __expf(m - mn);
        float p[GRP];
        float ps = 0.f;
        #pragma unroll
        for (int s = 0; s < GRP; ++s) { p[s] = __expf(e[s] - mn); ps += p[s]; }

        #pragma unroll
        for (int k = 0; k < 4; ++k) {
            acc[k].x *= sc; acc[k].y *= sc; acc[k].z *= sc; acc[k].w *= sc;
        }
        #pragma unroll
        for (int s = 0; s < GRP; ++s) {
            #pragma unroll
            for (int k = 0; k < 4; ++k) {
                acc[k].x += p[s] * d[s][k].x;
                acc[k].y += p[s] * d[s][k].y;
                acc[k].z += p[s] * d[s][k].z;
                acc[k].w += p[s] * d[s][k].w;
            }
        }
        l = l * sc + ps;
        m = mn;
    }

    float4* gp = reinterpret_cast<float4*>(g_partial + (size_t)bid * HIDDEN);
    gp[tid]       = acc[0];
    gp[tid + 256] = acc[1];
    gp[tid + 512] = acc[2];
    gp[tid + 768] = acc[3];
    if (tid == 0) { g_m[bid] = m; g_l[bid] = l; }

    // ---- grid barrier (all 256 blocks are co-resident) --------------------
    __threadfence();
    __syncthreads();
    if (tid == 0) {
        int t = atomicAdd(&g_count, 1);
        if (t == NBLK - 1) {
            g_count = 0;
            __threadfence();
            atomicExch(&g_phase, myphase + 1);
        } else {
            while (*(volatile int*)&g_phase == myphase) __nanosleep(64);
        }
    }
    __syncthreads();
    __threadfence();

    // ---- phase B: stats recompute (parallel, L2-hot) ----------------------
    float mt = g_m[tid];
    float lt = g_l[tid];

    float mv = mt;
    #pragma unroll
    for (int off = 16; off > 0; off >>= 1)
        mv = fmaxf(mv, __shfl_xor_sync(0xFFFFFFFFu, mv, off));
    if (lane == 0) red2[wid] = mv;
    __syncthreads();
    if (tid == 0) {
        float v = red2[0];
        #pragma unroll
        for (int i = 1; i < 8; ++i) v = fmaxf(v, red2[i]);
        sM = v;
    }
    __syncthreads();
    const float M = sM;

    float wexp = __expf(mt - M);
    float zt = lt * wexp;
    #pragma unroll
    for (int off = 16; off > 0; off >>= 1)
        zt += __shfl_xor_sync(0xFFFFFFFFu, zt, off);
    if (lane == 0) red2[wid] = zt;
    __syncthreads();
    if (tid == 0) {
        float v = red2[0];
        #pragma unroll
        for (int i = 1; i < 8; ++i) v += red2[i];
        sZ = v;
    }
    __syncthreads();
    const float invZ = 1.0f / sZ;
    const float wt = wexp * invZ;        // weight of partial-row `tid`

    // ---- phase C: combine — block owns float4 cols [4*bid, 4*bid+4) -------
    {
        const float4* pr = reinterpret_cast<const float4*>(g_partial + (size_t)tid * HIDDEN)
                         + bid * 4;
        #pragma unroll
        for (int k = 0; k < 4; ++k) {
            float4 v = pr[k];
            v.x *= wt; v.y *= wt; v.z *= wt; v.w *= wt;
            sacc[tid][k] = v;
        }
        __syncthreads();
        #pragma unroll
        for (int s = 128; s > 0; s >>= 1) {
            if (tid < s) {
                #pragma unroll
                for (int k = 0; k < 4; ++k) {
                    float4 a = sacc[tid][k];
                    float4 b = sacc[tid + s][k];
                    a.x += b.x; a.y += b.y; a.z += b.z; a.w += b.w;
                    sacc[tid][k] = a;
                }
            }
            __syncthreads();
        }
        if (tid < 16)
            out[bid * 16 + tid] = reinterpret_cast<const float*>(&sacc[0][0])[tid];
    }

    // ---- attn: block owns rows [32*bid, 32*bid+32) ------------------------
    if (tid < 32) {
        const int i = bid * 32 + tid;
        attn[i] = __expf(g_energies[i] - M) * invZ;
    }
}

extern "C" void kernel_launch(void* const* d_in, const int* in_sizes, int n_in,
                              void* d_out, int out_size)
{
    const float* hidden = (const float*)d_in[0];
    const float* enc    = (const float*)d_in[1];
    float* out  = (float*)d_out;
    float* attn = (float*)d_out + HIDDEN;

    attn_fused<<<NBLK, 256>>>(enc, hidden, out, attn);
}

// round 14
// speedup vs baseline: 1.0966x; 1.0966x over previous
#include <cuda_runtime.h>
#include <cuda_device_runtime_api.h>

// hidden [4096] f32, encoder_outputs [8192,1,4096] f32
// energies = enc @ hidden -> softmax -> output = enc^T @ attn
// d_out: [0:4096) = output, [4096:12288) = attn
//
// pass1: 512 blocks x 16 rows (4 groups of 4, one rescale per group);
//        last block finalizes stats. Triggers PDL after its stores.
// combine: R10's proven 16-colgroup x 32-bchunk scalar fold + attn write,
//          launched with programmatic stream serialization (PDL) so its
//          ramp overlaps pass1's tail.

#define SEQ_LEN 8192
#define HIDDEN  4096
#define H4      (HIDDEN / 4)
#define NBLK    512
#define ROWS    16                 // rows per pass1 block
#define GRP     4                  // rows per inner group
#define NGRP    (ROWS / GRP)       // 4
#define BCHUNK  16                 // partial rows per combine block
#define NBCH    (NBLK / BCHUNK)    // 32

__device__ float g_energies[SEQ_LEN];
__device__ float g_partial[(size_t)NBLK * HIDDEN];
__device__ float g_m[NBLK];
__device__ float g_l[NBLK];
__device__ float g_w[NBLK];        // exp(m_b - M) / Z
__device__ float g_stats[2];       // {M, invZ}
__device__ int   g_count;          // zero-init; reset by finalizer each launch

// ---------------------------------------------------------------------------
__global__ __launch_bounds__(256, 2) void pass1(
    const float* __restrict__ enc, const float* __restrict__ hidden,
    float* __restrict__ out)
{
    const int tid  = threadIdx.x;
    const int wid  = tid >> 5;
    const int lane = tid & 31;
    const int r0   = blockIdx.x * ROWS;

    if (blockIdx.x < 16) out[blockIdx.x * 256 + tid] = 0.f;

    __shared__ float sred[2][GRP][8];
    __shared__ int   s_last;

    const float4* h4 = reinterpret_cast<const float4*>(hidden);
    float4 hv0 = h4[tid];
    float4 hv1 = h4[tid + 256];
    float4 hv2 = h4[tid + 512];
    float4 hv3 = h4[tid + 768];

    float4 acc[4];
    #pragma unroll
    for (int k = 0; k < 4; ++k) acc[k] = make_float4(0.f, 0.f, 0.f, 0.f);
    float m = -3.4e38f;
    float l = 0.f;

    #pragma unroll 1
    for (int g = 0; g < NGRP; ++g) {
        const int rg = r0 + g * GRP;

        // 4 rows x 4 float4 = 16 independent loads, front-batched
        float4 d[GRP][4];
        #pragma unroll
        for (int s = 0; s < GRP; ++s) {
            const float4* b = reinterpret_cast<const float4*>(enc + (size_t)(rg + s) * HIDDEN);
            d[s][0] = b[tid];
            d[s][1] = b[tid + 256];
            d[s][2] = b[tid + 512];
            d[s][3] = b[tid + 768];
        }

        float dot[GRP];
        #pragma unroll
        for (int s = 0; s < GRP; ++s) {
            dot[s] = d[s][0].x*hv0.x + d[s][0].y*hv0.y + d[s][0].z*hv0.z + d[s][0].w*hv0.w
                   + d[s][1].x*hv1.x + d[s][1].y*hv1.y + d[s][1].z*hv1.z + d[s][1].w*hv1.w
                   + d[s][2].x*hv2.x + d[s][2].y*hv2.y + d[s][2].z*hv2.z + d[s][2].w*hv2.w
                   + d[s][3].x*hv3.x + d[s][3].y*hv3.y + d[s][3].z*hv3.z + d[s][3].w*hv3.w;
        }
        #pragma unroll
        for (int off = 16; off > 0; off >>= 1) {
            #pragma unroll
            for (int s = 0; s < GRP; ++s)
                dot[s] += __shfl_down_sync(0xFFFFFFFFu, dot[s], off);
        }
        if (lane == 0) {
            #pragma unroll
            for (int s = 0; s < GRP; ++s) sred[g & 1][s][wid] = dot[s];
        }
        __syncthreads();

        float e[GRP];
        #pragma unroll
        for (int s = 0; s < GRP; ++s)
            e[s] = sred[g & 1][s][0] + sred[g & 1][s][1] + sred[g & 1][s][2] + sred[g & 1][s][3]
                 + sred[g & 1][s][4] + sred[g & 1][s][5] + sred[g & 1][s][6] + sred[g & 1][s][7];
        if (tid < GRP) g_energies[rg + tid] = e[tid];

        // one online-rescale per group
        float mg = fmaxf(fmaxf(e[0], e[1]), fmaxf(e[2], e[3]));
        float mn = fmaxf(m, mg);
        float sc = __expf(m - mn);
        float p[GRP];
        float ps = 0.f;
        #pragma unroll
        for (int s = 0; s < GRP; ++s) { p[s] = __expf(e[s] - mn); ps += p[s]; }

        #pragma unroll
        for (int k = 0; k < 4; ++k) {
            acc[k].x *= sc; acc[k].y *= sc; acc[k].z *= sc; acc[k].w *= sc;
        }
        #pragma unroll
        for (int s = 0; s < GRP; ++s) {
            #pragma unroll
            for (int k = 0; k < 4; ++k) {
                acc[k].x += p[s] * d[s][k].x;
                acc[k].y += p[s] * d[s][k].y;
                acc[k].z += p[s] * d[s][k].z;
                acc[k].w += p[s] * d[s][k].w;
            }
        }
        l = l * sc + ps;
        m = mn;
    }

    float4* gp = reinterpret_cast<float4*>(g_partial + (size_t)blockIdx.x * HIDDEN);
    gp[tid]       = acc[0];
    gp[tid + 256] = acc[1];
    gp[tid + 512] = acc[2];
    gp[tid + 768] = acc[3];
    if (tid == 0) { g_m[blockIdx.x] = m; g_l[blockIdx.x] = l; }

    // PDL: allow the combine grid to begin launching; its griddepsync still
    // waits for this grid's full completion before consuming our writes.
    cudaTriggerProgrammaticLaunchCompletion();

    // ---- last-arriving block computes global stats + weights ----
    __threadfence();
    __syncthreads();
    if (tid == 0) {
        int t = atomicAdd(&g_count, 1);
        s_last = (t == NBLK - 1);
    }
    __syncthreads();
    if (!s_last) return;

    __shared__ float red2[8];
    __shared__ float sM, sZ;

    float mb0 = g_m[tid];
    float mb1 = g_m[tid + 256];
    float mv = fmaxf(mb0, mb1);
    #pragma unroll
    for (int off = 16; off > 0; off >>= 1)
        mv = fmaxf(mv, __shfl_xor_sync(0xFFFFFFFFu, mv, off));
    if (lane == 0) red2[wid] = mv;
    __syncthreads();
    if (tid == 0) {
        float v = red2[0];
        #pragma unroll
        for (int i = 1; i < 8; ++i) v = fmaxf(v, red2[i]);
        sM = v;
    }
    __syncthreads();
    float M = sM;

    float zt = g_l[tid] * __expf(mb0 - M) + g_l[tid + 256] * __expf(mb1 - M);
    #pragma unroll
    for (int off = 16; off > 0; off >>= 1)
        zt += __shfl_xor_sync(0xFFFFFFFFu, zt, off);
    if (lane == 0) red2[wid] = zt;
    __syncthreads();
    if (tid == 0) {
        float v = red2[0];
        #pragma unroll
        for (int i = 1; i < 8; ++i) v += red2[i];
        sZ = v;
    }
    __syncthreads();
    float invZ = 1.0f / sZ;

    g_w[tid]       = __expf(mb0 - M) * invZ;
    g_w[tid + 256] = __expf(mb1 - M) * invZ;
    if (tid == 0) { g_stats[0] = M; g_stats[1] = invZ; g_count = 0; }
}

// ---------------------------------------------------------------------------
// combine: blocks [0, 16*NBCH): col-group x b-chunk partial fold (atomic);
//          blocks [16*NBCH, +32): attn write. Launched with PDL.
__global__ __launch_bounds__(256) void combine(
    float* __restrict__ out, float* __restrict__ attn)
{
    const int tid = threadIdx.x;
    const int gid = blockIdx.x;

    // Preamble (index math / shared decl) happens pre-sync; then wait for
    // pass1's memory to be visible.
    __shared__ float w[BCHUNK];
    const int col = (gid & 15) * 256 + tid;
    const int b0  = (gid >> 4) * BCHUNK;

    cudaGridDependencySynchronize();

    if (gid < 16 * NBCH) {
        if (tid < BCHUNK) w[tid] = g_w[b0 + tid];
        __syncthreads();

        float acc = 0.f;
        #pragma unroll
        for (int j = 0; j < BCHUNK; ++j)
            acc += g_partial[(size_t)(b0 + j) * HIDDEN + col] * w[j];
        atomicAdd(&out[col], acc);
    } else {
        const float M    = g_stats[0];
        const float invZ = g_stats[1];
        const int i = (gid - 16 * NBCH) * 256 + tid;
        attn[i] = __expf(g_energies[i] - M) * invZ;
    }
}

extern "C" void kernel_launch(void* const* d_in, const int* in_sizes, int n_in,
                              void* d_out, int out_size)
{
    const float* hidden = (const float*)d_in[0];
    const float* enc    = (const float*)d_in[1];
    float* out  = (float*)d_out;
    float* attn = (float*)d_out + HIDDEN;

    pass1<<<NBLK, 256>>>(enc, hidden, out);

    // Launch combine with programmatic stream serialization (PDL)
    cudaLaunchConfig_t cfg = {};
    cfg.gridDim  = dim3(16 * NBCH + SEQ_LEN / 256, 1, 1);
    cfg.blockDim = dim3(256, 1, 1);
    cfg.dynamicSmemBytes = 0;
    cfg.stream = 0;
    cudaLaunchAttribute attr[1];
    attr[0].id = cudaLaunchAttributeProgrammaticStreamSerialization;
    attr[0].val.programmaticStreamSerializationAllowed = 1;
    cfg.attrs = attr;
    cfg.numAttrs = 1;
    cudaLaunchKernelEx(&cfg, combine, out, attn);
}

// round 15
// speedup vs baseline: 1.1289x; 1.0294x over previous
#include <cuda_runtime.h>

// hidden [4096] f32, encoder_outputs [8192,1,4096] f32
// energies = enc @ hidden -> softmax -> output = enc^T @ attn
// d_out: [0:4096) = output, [4096:12288) = attn
//
// pass1: 512 blocks x 16 rows (4 groups of 4, one rescale per group);
//        enc loads use __ldcs (evict-first) so partials stay L2-resident.
//        Last block finalizes stats.
// combine: R10's 16-colgroup x 32-bchunk fold + attn write (now L2-hot).

#define SEQ_LEN 8192
#define HIDDEN  4096
#define H4      (HIDDEN / 4)
#define NBLK    512
#define ROWS    16                 // rows per pass1 block
#define GRP     4                  // rows per inner group
#define NGRP    (ROWS / GRP)       // 4
#define BCHUNK  16                 // partial rows per combine block
#define NBCH    (NBLK / BCHUNK)    // 32

__device__ float g_energies[SEQ_LEN];
__device__ float g_partial[(size_t)NBLK * HIDDEN];
__device__ float g_m[NBLK];
__device__ float g_l[NBLK];
__device__ float g_w[NBLK];        // exp(m_b - M) / Z
__device__ float g_stats[2];       // {M, invZ}
__device__ int   g_count;          // zero-init; reset by finalizer each launch

// ---------------------------------------------------------------------------
__global__ __launch_bounds__(256, 2) void pass1(
    const float* __restrict__ enc, const float* __restrict__ hidden,
    float* __restrict__ out)
{
    const int tid  = threadIdx.x;
    const int wid  = tid >> 5;
    const int lane = tid & 31;
    const int r0   = blockIdx.x * ROWS;

    if (blockIdx.x < 16) out[blockIdx.x * 256 + tid] = 0.f;

    __shared__ float sred[2][GRP][8];
    __shared__ int   s_last;

    const float4* h4 = reinterpret_cast<const float4*>(hidden);
    float4 hv0 = h4[tid];
    float4 hv1 = h4[tid + 256];
    float4 hv2 = h4[tid + 512];
    float4 hv3 = h4[tid + 768];

    float4 acc[4];
    #pragma unroll
    for (int k = 0; k < 4; ++k) acc[k] = make_float4(0.f, 0.f, 0.f, 0.f);
    float m = -3.4e38f;
    float l = 0.f;

    #pragma unroll 1
    for (int g = 0; g < NGRP; ++g) {
        const int rg = r0 + g * GRP;

        // 4 rows x 4 float4 = 16 independent loads, front-batched,
        // evict-first (enc has no reuse; protect partials in L2)
        float4 d[GRP][4];
        #pragma unroll
        for (int s = 0; s < GRP; ++s) {
            const float4* b = reinterpret_cast<const float4*>(enc + (size_t)(rg + s) * HIDDEN);
            d[s][0] = __ldcs(b + tid);
            d[s][1] = __ldcs(b + tid + 256);
            d[s][2] = __ldcs(b + tid + 512);
            d[s][3] = __ldcs(b + tid + 768);
        }

        float dot[GRP];
        #pragma unroll
        for (int s = 0; s < GRP; ++s) {
            dot[s] = d[s][0].x*hv0.x + d[s][0].y*hv0.y + d[s][0].z*hv0.z + d[s][0].w*hv0.w
                   + d[s][1].x*hv1.x + d[s][1].y*hv1.y + d[s][1].z*hv1.z + d[s][1].w*hv1.w
                   + d[s][2].x*hv2.x + d[s][2].y*hv2.y + d[s][2].z*hv2.z + d[s][2].w*hv2.w
                   + d[s][3].x*hv3.x + d[s][3].y*hv3.y + d[s][3].z*hv3.z + d[s][3].w*hv3.w;
        }
        #pragma unroll
        for (int off = 16; off > 0; off >>= 1) {
            #pragma unroll
            for (int s = 0; s < GRP; ++s)
                dot[s] += __shfl_down_sync(0xFFFFFFFFu, dot[s], off);
        }
        if (lane == 0) {
            #pragma unroll
            for (int s = 0; s < GRP; ++s) sred[g & 1][s][wid] = dot[s];
        }
        __syncthreads();

        float e[GRP];
        #pragma unroll
        for (int s = 0; s < GRP; ++s)
            e[s] = sred[g & 1][s][0] + sred[g & 1][s][1] + sred[g & 1][s][2] + sred[g & 1][s][3]
                 + sred[g & 1][s][4] + sred[g & 1][s][5] + sred[g & 1][s][6] + sred[g & 1][s][7];
        if (tid < GRP) g_energies[rg + tid] = e[tid];

        // one online-rescale per group
        float mg = fmaxf(fmaxf(e[0], e[1]), fmaxf(e[2], e[3]));
        float mn = fmaxf(m, mg);
        float sc = __expf(m - mn);
        float p[GRP];
        float ps = 0.f;
        #pragma unroll
        for (int s = 0; s < GRP; ++s) { p[s] = __expf(e[s] - mn); ps += p[s]; }

        #pragma unroll
        for (int k = 0; k < 4; ++k) {
            acc[k].x *= sc; acc[k].y *= sc; acc[k].z *= sc; acc[k].w *= sc;
        }
        #pragma unroll
        for (int s = 0; s < GRP; ++s) {
            #pragma unroll
            for (int k = 0; k < 4; ++k) {
                acc[k].x += p[s] * d[s][k].x;
                acc[k].y += p[s] * d[s][k].y;
                acc[k].z += p[s] * d[s][k].z;
                acc[k].w += p[s] * d[s][k].w;
            }
        }
        l = l * sc + ps;
        m = mn;
    }

    float4* gp = reinterpret_cast<float4*>(g_partial + (size_t)blockIdx.x * HIDDEN);
    gp[tid]       = acc[0];
    gp[tid + 256] = acc[1];
    gp[tid + 512] = acc[2];
    gp[tid + 768] = acc[3];
    if (tid == 0) { g_m[blockIdx.x] = m; g_l[blockIdx.x] = l; }

    // ---- last-arriving block computes global stats + weights ----
    __threadfence();
    __syncthreads();
    if (tid == 0) {
        int t = atomicAdd(&g_count, 1);
        s_last = (t == NBLK - 1);
    }
    __syncthreads();
    if (!s_last) return;

    __shared__ float red2[8];
    __shared__ float sM, sZ;

    float mb0 = g_m[tid];
    float mb1 = g_m[tid + 256];
    float mv = fmaxf(mb0, mb1);
    #pragma unroll
    for (int off = 16; off > 0; off >>= 1)
        mv = fmaxf(mv, __shfl_xor_sync(0xFFFFFFFFu, mv, off));
    if (lane == 0) red2[wid] = mv;
    __syncthreads();
    if (tid == 0) {
        float v = red2[0];
        #pragma unroll
        for (int i = 1; i < 8; ++i) v = fmaxf(v, red2[i]);
        sM = v;
    }
    __syncthreads();
    float M = sM;

    float zt = g_l[tid] * __expf(mb0 - M) + g_l[tid + 256] * __expf(mb1 - M);
    #pragma unroll
    for (int off = 16; off > 0; off >>= 1)
        zt += __shfl_xor_sync(0xFFFFFFFFu, zt, off);
    if (lane == 0) red2[wid] = zt;
    __syncthreads();
    if (tid == 0) {
        float v = red2[0];
        #pragma unroll
        for (int i = 1; i < 8; ++i) v += red2[i];
        sZ = v;
    }
    __syncthreads();
    float invZ = 1.0f / sZ;

    g_w[tid]       = __expf(mb0 - M) * invZ;
    g_w[tid + 256] = __expf(mb1 - M) * invZ;
    if (tid == 0) { g_stats[0] = M; g_stats[1] = invZ; g_count = 0; }
}

// ---------------------------------------------------------------------------
// combine: blocks [0, 16*NBCH): col-group x b-chunk partial fold (atomic);
//          blocks [16*NBCH, +32): attn write.
__global__ __launch_bounds__(256) void combine(
    float* __restrict__ out, float* __restrict__ attn)
{
    const int tid = threadIdx.x;
    const int gid = blockIdx.x;

    if (gid < 16 * NBCH) {
        __shared__ float w[BCHUNK];
        const int col = (gid & 15) * 256 + tid;
        const int b0  = (gid >> 4) * BCHUNK;
        if (tid < BCHUNK) w[tid] = g_w[b0 + tid];
        __syncthreads();

        float acc = 0.f;
        #pragma unroll
        for (int j = 0; j < BCHUNK; ++j)
            acc += g_partial[(size_t)(b0 + j) * HIDDEN + col] * w[j];
        atomicAdd(&out[col], acc);
    } else {
        const float M    = g_stats[0];
        const float invZ = g_stats[1];
        const int i = (gid - 16 * NBCH) * 256 + tid;
        attn[i] = __expf(g_energies[i] - M) * invZ;
    }
}

extern "C" void kernel_launch(void* const* d_in, const int* in_sizes, int n_in,
                              void* d_out, int out_size)
{
    const float* hidden = (const float*)d_in[0];
    const float* enc    = (const float*)d_in[1];
    float* out  = (float*)d_out;
    float* attn = (float*)d_out + HIDDEN;

    pass1<<<NBLK, 256>>>(enc, hidden, out);
    combine<<<16 * NBCH + SEQ_LEN / 256, 256>>>(out, attn);
}